// round 1
// baseline (speedup 1.0000x reference)
#include <cuda_runtime.h>
#include <math.h>

// ---------------- problem constants ----------------
constexpr int kNL = 4;
constexpr int kD  = 1024;
constexpr int kD2 = 2048;
constexpr int kH  = 16;
constexpr int kDH = 64;
constexpr int kV  = 32000;
constexpr int kB  = 2;
constexpr int kL  = 2048;
constexpr int kBL = kB * kL;   // 4096
#define EPSF 1e-6f

// ---------------- scratch (device globals; no allocation allowed) ----------------
__device__ float g_x[kBL * kD];
__device__ float g_h[kBL * kD];
__device__ float g_q[kBL * kD];
__device__ float g_k[kBL * kD];
__device__ float g_v[kBL * kD];
__device__ float g_att[kBL * kD];
__device__ float g_proj[(size_t)kBL * kD2];
__device__ float g_up[(size_t)kBL * kD2];

// ---------------- embed + positional encoding ----------------
// pe[:,2i] = sin(pos * exp(2i * (-log(10000)/D))), pe[:,2i+1] = cos(same)
__global__ void embed_pe_kernel(const int* __restrict__ ids,
                                const float* __restrict__ embed,
                                float* __restrict__ x)
{
    int row = blockIdx.x;             // 0..kBL-1  (b*L + l)
    int l   = row % kL;
    int id  = ids[row];
    int d0  = threadIdx.x * 4;        // 256 threads * 4 = 1024
    float4 ev = *(const float4*)&embed[(size_t)id * kD + d0];
    float out[4] = {ev.x, ev.y, ev.z, ev.w};
    // fp32 constant matching jnp: -log(10000)/1024
    const float negc = -0.0089944731f;
#pragma unroll
    for (int t = 0; t < 4; ++t) {
        int d  = d0 + t;
        int i2 = (d >> 1) * 2;
        float freq = expf((float)i2 * negc);
        float a    = (float)l * freq;
        out[t] += (d & 1) ? cosf(a) : sinf(a);
    }
    *(float4*)&x[(size_t)row * kD + d0] = make_float4(out[0], out[1], out[2], out[3]);
}

// ---------------- rmsnorm ----------------
__global__ void rmsnorm_kernel(const float* __restrict__ x,
                               const float* __restrict__ gamma,
                               float* __restrict__ y)
{
    int row = blockIdx.x;
    const float* xr = x + (size_t)row * kD;
    int d0 = threadIdx.x * 4;
    float4 v = *(const float4*)&xr[d0];
    float ss = v.x * v.x + v.y * v.y + v.z * v.z + v.w * v.w;
#pragma unroll
    for (int off = 16; off; off >>= 1)
        ss += __shfl_xor_sync(0xffffffffu, ss, off);
    __shared__ float ws[8];
    int lane = threadIdx.x & 31, w = threadIdx.x >> 5;
    if (lane == 0) ws[w] = ss;
    __syncthreads();
    if (w == 0) {
        float t = (lane < 8) ? ws[lane] : 0.0f;
#pragma unroll
        for (int off = 4; off; off >>= 1)
            t += __shfl_xor_sync(0xffffffffu, t, off);
        if (lane == 0) ws[0] = t;
    }
    __syncthreads();
    float scale = rsqrtf(ws[0] / (float)kD + EPSF);
    float4 g = *(const float4*)&gamma[d0];
    float4 o = make_float4(v.x * scale * g.x, v.y * scale * g.y,
                           v.z * scale * g.z, v.w * scale * g.w);
    *(float4*)&y[(size_t)row * kD + d0] = o;
}

// ---------------- silu gate: proj = silu(proj * up) ----------------
__global__ void silu_gate_kernel(float* __restrict__ proj,
                                 const float* __restrict__ up)
{
    size_t i = ((size_t)blockIdx.x * blockDim.x + threadIdx.x) * 4;
    float4 p = *(float4*)&proj[i];
    float4 u = *(const float4*)&up[i];
    float t0 = p.x * u.x, t1 = p.y * u.y, t2 = p.z * u.z, t3 = p.w * u.w;
    p.x = t0 / (1.0f + __expf(-t0));
    p.y = t1 / (1.0f + __expf(-t1));
    p.z = t2 / (1.0f + __expf(-t2));
    p.w = t3 / (1.0f + __expf(-t3));
    *(float4*)&proj[i] = p;
}

// ---------------- SGEMM: C = A[M,K] @ B[K,N] + bias[N] (+ resid[M,N]) ----------------
// BM=BN=128, BK=16, 256 threads, 8x8 per-thread tile. Requires M%128==0, N%128==0, K%16==0.
__global__ void __launch_bounds__(256)
sgemm_bias_kernel(const float* __restrict__ A, const float* __restrict__ Bw,
                  const float* __restrict__ bias, const float* __restrict__ resid,
                  float* __restrict__ C, int M, int N, int K)
{
    __shared__ float As[16][128];
    __shared__ float Bs[16][128];
    int tid = threadIdx.x;
    int tx = tid & 15, ty = tid >> 4;
    int bm = blockIdx.y, bn = blockIdx.x;
    const float* Ab = A + (size_t)bm * 128 * K;
    const float* Bb = Bw + (size_t)bn * 128;

    int arow = tid >> 2;          // 0..63
    int acol = (tid & 3) * 4;     // 0,4,8,12
    int brow = tid >> 5;          // 0..7
    int bcol = (tid & 31) * 4;    // 0..124

    float acc[8][8];
#pragma unroll
    for (int i = 0; i < 8; ++i)
#pragma unroll
        for (int j = 0; j < 8; ++j) acc[i][j] = 0.0f;

    for (int k0 = 0; k0 < K; k0 += 16) {
        float4 a0 = *(const float4*)&Ab[(size_t)arow * K + k0 + acol];
        float4 a1 = *(const float4*)&Ab[(size_t)(arow + 64) * K + k0 + acol];
        float4 b0 = *(const float4*)&Bb[(size_t)(k0 + brow) * N + bcol];
        float4 b1 = *(const float4*)&Bb[(size_t)(k0 + brow + 8) * N + bcol];
        __syncthreads();
        As[acol + 0][arow] = a0.x; As[acol + 1][arow] = a0.y;
        As[acol + 2][arow] = a0.z; As[acol + 3][arow] = a0.w;
        As[acol + 0][arow + 64] = a1.x; As[acol + 1][arow + 64] = a1.y;
        As[acol + 2][arow + 64] = a1.z; As[acol + 3][arow + 64] = a1.w;
        *(float4*)&Bs[brow][bcol]     = b0;
        *(float4*)&Bs[brow + 8][bcol] = b1;
        __syncthreads();
#pragma unroll
        for (int kk = 0; kk < 16; ++kk) {
            float a[8], b[8];
            *(float4*)&a[0] = *(float4*)&As[kk][ty * 8];
            *(float4*)&a[4] = *(float4*)&As[kk][ty * 8 + 4];
            *(float4*)&b[0] = *(float4*)&Bs[kk][tx * 8];
            *(float4*)&b[4] = *(float4*)&Bs[kk][tx * 8 + 4];
#pragma unroll
            for (int i = 0; i < 8; ++i)
#pragma unroll
                for (int j = 0; j < 8; ++j)
                    acc[i][j] = fmaf(a[i], b[j], acc[i][j]);
        }
    }

    int crow0 = bm * 128 + ty * 8;
    int ccol0 = bn * 128 + tx * 8;
    float bb[8];
    *(float4*)&bb[0] = *(const float4*)&bias[ccol0];
    *(float4*)&bb[4] = *(const float4*)&bias[ccol0 + 4];
#pragma unroll
    for (int i = 0; i < 8; ++i) {
        size_t off = (size_t)(crow0 + i) * N + ccol0;
        float v[8];
#pragma unroll
        for (int j = 0; j < 8; ++j) v[j] = acc[i][j] + bb[j];
        if (resid) {
            float4 r0 = *(const float4*)&resid[off];
            float4 r1 = *(const float4*)&resid[off + 4];
            v[0] += r0.x; v[1] += r0.y; v[2] += r0.z; v[3] += r0.w;
            v[4] += r1.x; v[5] += r1.y; v[6] += r1.z; v[7] += r1.w;
        }
        *(float4*)&C[off]     = make_float4(v[0], v[1], v[2], v[3]);
        *(float4*)&C[off + 4] = make_float4(v[4], v[5], v[6], v[7]);
    }
}

// ---------------- flash attention (causal, dh=64, 64-query tiles) ----------------
// grid: (L/64, B*H), 256 threads (16x16 logical), per-thread 4x4 tiles.
// smem: Qs[64][65] (j-major), Ks[64][65] (j-major), Vs[64][68] (key-major), Ps[64][65] (key-major)
constexpr int kFlashSmem = (2 * 64 * 65 + 64 * 68 + 64 * 65) * 4;  // 67328 bytes

__global__ void __launch_bounds__(256)
flash_attn_kernel(const float* __restrict__ Q, const float* __restrict__ K,
                  const float* __restrict__ Vv, float* __restrict__ O)
{
    extern __shared__ float sm[];
    float* Qs = sm;                    // [j][row] pitch 65
    float* Ks = sm + 64 * 65;          // [j][key] pitch 65
    float* Vs = sm + 2 * 64 * 65;      // [key][j] pitch 68
    float* Ps = Vs + 64 * 68;          // [key][row] pitch 65

    int bh = blockIdx.y;
    int b  = bh / kH;
    int h  = bh % kH;
    int q0 = blockIdx.x * 64;
    int tid = threadIdx.x;
    int tx = tid & 15, ty = tid >> 4;
    size_t base = ((size_t)b * kL) * kD + (size_t)h * kDH;

    // load Q (transposed into smem)
#pragma unroll
    for (int rr = 0; rr < 4; ++rr) {
        int r = (tid >> 4) + rr * 16;
        int j = (tid & 15) * 4;
        float4 qv = *(const float4*)&Q[base + (size_t)(q0 + r) * kD + j];
        Qs[(j + 0) * 65 + r] = qv.x; Qs[(j + 1) * 65 + r] = qv.y;
        Qs[(j + 2) * 65 + r] = qv.z; Qs[(j + 3) * 65 + r] = qv.w;
    }

    float o[4][4];
    float m[4], lsum[4];
#pragma unroll
    for (int r = 0; r < 4; ++r) {
        m[r] = -1e30f; lsum[r] = 0.0f;
#pragma unroll
        for (int c = 0; c < 4; ++c) o[r][c] = 0.0f;
    }

    int nkt = blockIdx.x + 1;   // causal: key tiles 0..qtile
    for (int kt = 0; kt < nkt; ++kt) {
        int k0 = kt * 64;
        __syncthreads();        // prior PV gemm done before overwriting Ks/Vs
#pragma unroll
        for (int rr = 0; rr < 4; ++rr) {
            int r = (tid >> 4) + rr * 16;
            int j = (tid & 15) * 4;
            float4 kv = *(const float4*)&K[base + (size_t)(k0 + r) * kD + j];
            Ks[(j + 0) * 65 + r] = kv.x; Ks[(j + 1) * 65 + r] = kv.y;
            Ks[(j + 2) * 65 + r] = kv.z; Ks[(j + 3) * 65 + r] = kv.w;
            float4 vv = *(const float4*)&Vv[base + (size_t)(k0 + r) * kD + j];
            *(float4*)&Vs[r * 68 + j] = vv;
        }
        __syncthreads();

        // S = Q @ K^T  (4x4 per thread)
        float s[4][4];
#pragma unroll
        for (int r = 0; r < 4; ++r)
#pragma unroll
            for (int c = 0; c < 4; ++c) s[r][c] = 0.0f;
#pragma unroll
        for (int j = 0; j < kDH; ++j) {
            float a0 = Qs[j * 65 + ty * 4 + 0];
            float a1 = Qs[j * 65 + ty * 4 + 1];
            float a2 = Qs[j * 65 + ty * 4 + 2];
            float a3 = Qs[j * 65 + ty * 4 + 3];
            float b0 = Ks[j * 65 + tx * 4 + 0];
            float b1 = Ks[j * 65 + tx * 4 + 1];
            float b2 = Ks[j * 65 + tx * 4 + 2];
            float b3 = Ks[j * 65 + tx * 4 + 3];
            s[0][0] = fmaf(a0, b0, s[0][0]); s[0][1] = fmaf(a0, b1, s[0][1]);
            s[0][2] = fmaf(a0, b2, s[0][2]); s[0][3] = fmaf(a0, b3, s[0][3]);
            s[1][0] = fmaf(a1, b0, s[1][0]); s[1][1] = fmaf(a1, b1, s[1][1]);
            s[1][2] = fmaf(a1, b2, s[1][2]); s[1][3] = fmaf(a1, b3, s[1][3]);
            s[2][0] = fmaf(a2, b0, s[2][0]); s[2][1] = fmaf(a2, b1, s[2][1]);
            s[2][2] = fmaf(a2, b2, s[2][2]); s[2][3] = fmaf(a2, b3, s[2][3]);
            s[3][0] = fmaf(a3, b0, s[3][0]); s[3][1] = fmaf(a3, b1, s[3][1]);
            s[3][2] = fmaf(a3, b2, s[3][2]); s[3][3] = fmaf(a3, b3, s[3][3]);
        }

        bool diag = (kt == blockIdx.x);
#pragma unroll
        for (int r = 0; r < 4; ++r)
#pragma unroll
            for (int c = 0; c < 4; ++c) {
                float sv = s[r][c] * 0.125f;   // 1/sqrt(64)
                if (diag && (k0 + tx * 4 + c > q0 + ty * 4 + r)) sv = -1e30f;
                s[r][c] = sv;
            }

        // row max across the 16 threads (same ty) that own each row
        float corr[4];
#pragma unroll
        for (int r = 0; r < 4; ++r) {
            float rm = fmaxf(fmaxf(s[r][0], s[r][1]), fmaxf(s[r][2], s[r][3]));
#pragma unroll
            for (int off = 8; off; off >>= 1)
                rm = fmaxf(rm, __shfl_xor_sync(0xffffffffu, rm, off));
            float mn = fmaxf(m[r], rm);
            corr[r] = __expf(m[r] - mn);
            m[r] = mn;
        }
        // P = exp(S - m), accumulate row sums, stage P to smem (key-major)
        float rs[4];
#pragma unroll
        for (int r = 0; r < 4; ++r) {
            rs[r] = 0.0f;
#pragma unroll
            for (int c = 0; c < 4; ++c) {
                float p = __expf(s[r][c] - m[r]);
                Ps[(tx * 4 + c) * 65 + ty * 4 + r] = p;
                rs[r] += p;
            }
#pragma unroll
            for (int off = 8; off; off >>= 1)
                rs[r] += __shfl_xor_sync(0xffffffffu, rs[r], off);
            lsum[r] = lsum[r] * corr[r] + rs[r];
#pragma unroll
            for (int c = 0; c < 4; ++c) o[r][c] *= corr[r];
        }
        __syncthreads();

        // O += P @ V
#pragma unroll
        for (int key = 0; key < 64; ++key) {
            float pa0 = Ps[key * 65 + ty * 4 + 0];
            float pa1 = Ps[key * 65 + ty * 4 + 1];
            float pa2 = Ps[key * 65 + ty * 4 + 2];
            float pa3 = Ps[key * 65 + ty * 4 + 3];
            float vb0 = Vs[key * 68 + tx * 4 + 0];
            float vb1 = Vs[key * 68 + tx * 4 + 1];
            float vb2 = Vs[key * 68 + tx * 4 + 2];
            float vb3 = Vs[key * 68 + tx * 4 + 3];
            o[0][0] = fmaf(pa0, vb0, o[0][0]); o[0][1] = fmaf(pa0, vb1, o[0][1]);
            o[0][2] = fmaf(pa0, vb2, o[0][2]); o[0][3] = fmaf(pa0, vb3, o[0][3]);
            o[1][0] = fmaf(pa1, vb0, o[1][0]); o[1][1] = fmaf(pa1, vb1, o[1][1]);
            o[1][2] = fmaf(pa1, vb2, o[1][2]); o[1][3] = fmaf(pa1, vb3, o[1][3]);
            o[2][0] = fmaf(pa2, vb0, o[2][0]); o[2][1] = fmaf(pa2, vb1, o[2][1]);
            o[2][2] = fmaf(pa2, vb2, o[2][2]); o[2][3] = fmaf(pa2, vb3, o[2][3]);
            o[3][0] = fmaf(pa3, vb0, o[3][0]); o[3][1] = fmaf(pa3, vb1, o[3][1]);
            o[3][2] = fmaf(pa3, vb2, o[3][2]); o[3][3] = fmaf(pa3, vb3, o[3][3]);
        }
    }

    // epilogue: normalize and write
#pragma unroll
    for (int r = 0; r < 4; ++r) {
        float inv = 1.0f / lsum[r];
        int gr = q0 + ty * 4 + r;
        float4 ov = make_float4(o[r][0] * inv, o[r][1] * inv, o[r][2] * inv, o[r][3] * inv);
        *(float4*)&O[base + (size_t)gr * kD + tx * 4] = ov;
    }
}

// ---------------- host launcher ----------------
extern "C" void kernel_launch(void* const* d_in, const int* in_sizes, int n_in,
                              void* d_out, int out_size)
{
    const int*   ids    = (const int*)  d_in[0];
    const float* embed  = (const float*)d_in[1];
    const float* Wq     = (const float*)d_in[2];
    const float* bq     = (const float*)d_in[3];
    const float* Wk     = (const float*)d_in[4];
    const float* bk     = (const float*)d_in[5];
    const float* Wv     = (const float*)d_in[6];
    const float* bv     = (const float*)d_in[7];
    const float* Wo     = (const float*)d_in[8];
    const float* bo     = (const float*)d_in[9];
    const float* Wproj  = (const float*)d_in[10];
    const float* bproj  = (const float*)d_in[11];
    const float* Wup    = (const float*)d_in[12];
    const float* bup    = (const float*)d_in[13];
    const float* Wdown  = (const float*)d_in[14];
    const float* bdown  = (const float*)d_in[15];
    const float* gammas = (const float*)d_in[16];
    const float* Wlog   = (const float*)d_in[17];
    const float* blog   = (const float*)d_in[18];
    float* out = (float*)d_out;

    float *x, *h, *q, *k, *v, *att, *proj, *up;
    cudaGetSymbolAddress((void**)&x,    g_x);
    cudaGetSymbolAddress((void**)&h,    g_h);
    cudaGetSymbolAddress((void**)&q,    g_q);
    cudaGetSymbolAddress((void**)&k,    g_k);
    cudaGetSymbolAddress((void**)&v,    g_v);
    cudaGetSymbolAddress((void**)&att,  g_att);
    cudaGetSymbolAddress((void**)&proj, g_proj);
    cudaGetSymbolAddress((void**)&up,   g_up);

    cudaFuncSetAttribute(flash_attn_kernel,
                         cudaFuncAttributeMaxDynamicSharedMemorySize, kFlashSmem);

    embed_pe_kernel<<<kBL, 256>>>(ids, embed, x);

    dim3 gD (kD  / 128, kBL / 128);  // N=1024
    dim3 gD2(kD2 / 128, kBL / 128);  // N=2048
    dim3 gV (kV  / 128, kBL / 128);  // N=32000

    for (int i = 0; i < kNL; ++i) {
        rmsnorm_kernel<<<kBL, 256>>>(x, gammas + (size_t)(2 * i) * kD, h);
        sgemm_bias_kernel<<<gD, 256>>>(h, Wq + (size_t)i * kD * kD, bq + (size_t)i * kD,
                                       nullptr, q, kBL, kD, kD);
        sgemm_bias_kernel<<<gD, 256>>>(h, Wk + (size_t)i * kD * kD, bk + (size_t)i * kD,
                                       nullptr, k, kBL, kD, kD);
        sgemm_bias_kernel<<<gD, 256>>>(h, Wv + (size_t)i * kD * kD, bv + (size_t)i * kD,
                                       nullptr, v, kBL, kD, kD);
        flash_attn_kernel<<<dim3(kL / 64, kB * kH), 256, kFlashSmem>>>(q, k, v, att);
        sgemm_bias_kernel<<<gD, 256>>>(att, Wo + (size_t)i * kD * kD, bo + (size_t)i * kD,
                                       x, x, kBL, kD, kD);  // residual add
        rmsnorm_kernel<<<kBL, 256>>>(x, gammas + (size_t)(2 * i + 1) * kD, h);
        sgemm_bias_kernel<<<gD2, 256>>>(h, Wproj + (size_t)i * kD * kD2, bproj + (size_t)i * kD2,
                                        nullptr, proj, kBL, kD2, kD);
        sgemm_bias_kernel<<<gD2, 256>>>(h, Wup + (size_t)i * kD * kD2, bup + (size_t)i * kD2,
                                        nullptr, up, kBL, kD2, kD);
        silu_gate_kernel<<<((size_t)kBL * kD2) / (256 * 4), 256>>>(proj, up);
        sgemm_bias_kernel<<<gD, 256>>>(proj, Wdown + (size_t)i * kD2 * kD, bdown + (size_t)i * kD,
                                       x, x, kBL, kD, kD2); // residual add
    }
    sgemm_bias_kernel<<<gV, 256>>>(x, Wlog, blog, nullptr, out, kBL, kV, kD);
}

// round 2
// speedup vs baseline: 2.2300x; 2.2300x over previous
#include <cuda_runtime.h>
#include <math.h>
#include <stdint.h>

// ---------------- problem constants ----------------
constexpr int kNL = 4;
constexpr int kD  = 1024;
constexpr int kD2 = 2048;
constexpr int kH  = 16;
constexpr int kDH = 64;
constexpr int kV  = 32000;
constexpr int kB  = 2;
constexpr int kL  = 2048;
constexpr int kBL = kB * kL;   // 4096
#define EPSF 1e-6f

// ---------------- scratch (device globals; no allocation allowed) ----------------
__device__ float g_x[kBL * kD];
__device__ float g_h[kBL * kD];
__device__ float g_q[kBL * kD];
__device__ float g_k[kBL * kD];
__device__ float g_v[kBL * kD];
__device__ float g_att[kBL * kD];
__device__ float g_proj[(size_t)kBL * kD2];
__device__ float g_up[(size_t)kBL * kD2];

// ---------------- embed + positional encoding ----------------
__global__ void embed_pe_kernel(const int* __restrict__ ids,
                                const float* __restrict__ embed,
                                float* __restrict__ x)
{
    int row = blockIdx.x;
    int l   = row % kL;
    int id  = ids[row];
    int d0  = threadIdx.x * 4;
    float4 ev = *(const float4*)&embed[(size_t)id * kD + d0];
    float out[4] = {ev.x, ev.y, ev.z, ev.w};
    const float negc = -0.0089944731f;   // -log(10000)/1024 in fp32
#pragma unroll
    for (int t = 0; t < 4; ++t) {
        int d  = d0 + t;
        int i2 = (d >> 1) * 2;
        float freq = expf((float)i2 * negc);
        float a    = (float)l * freq;
        out[t] += (d & 1) ? cosf(a) : sinf(a);
    }
    *(float4*)&x[(size_t)row * kD + d0] = make_float4(out[0], out[1], out[2], out[3]);
}

// ---------------- rmsnorm ----------------
__global__ void rmsnorm_kernel(const float* __restrict__ x,
                               const float* __restrict__ gamma,
                               float* __restrict__ y)
{
    int row = blockIdx.x;
    const float* xr = x + (size_t)row * kD;
    int d0 = threadIdx.x * 4;
    float4 v = *(const float4*)&xr[d0];
    float ss = v.x * v.x + v.y * v.y + v.z * v.z + v.w * v.w;
#pragma unroll
    for (int off = 16; off; off >>= 1)
        ss += __shfl_xor_sync(0xffffffffu, ss, off);
    __shared__ float ws[8];
    int lane = threadIdx.x & 31, w = threadIdx.x >> 5;
    if (lane == 0) ws[w] = ss;
    __syncthreads();
    if (w == 0) {
        float t = (lane < 8) ? ws[lane] : 0.0f;
#pragma unroll
        for (int off = 4; off; off >>= 1)
            t += __shfl_xor_sync(0xffffffffu, t, off);
        if (lane == 0) ws[0] = t;
    }
    __syncthreads();
    float scale = rsqrtf(ws[0] / (float)kD + EPSF);
    float4 g = *(const float4*)&gamma[d0];
    float4 o = make_float4(v.x * scale * g.x, v.y * scale * g.y,
                           v.z * scale * g.z, v.w * scale * g.w);
    *(float4*)&y[(size_t)row * kD + d0] = o;
}

// ---------------- silu gate: proj = silu(proj * up) ----------------
__global__ void silu_gate_kernel(float* __restrict__ proj,
                                 const float* __restrict__ up)
{
    size_t i = ((size_t)blockIdx.x * blockDim.x + threadIdx.x) * 4;
    float4 p = *(float4*)&proj[i];
    float4 u = *(const float4*)&up[i];
    float t0 = p.x * u.x, t1 = p.y * u.y, t2 = p.z * u.z, t3 = p.w * u.w;
    p.x = t0 / (1.0f + __expf(-t0));
    p.y = t1 / (1.0f + __expf(-t1));
    p.z = t2 / (1.0f + __expf(-t2));
    p.w = t3 / (1.0f + __expf(-t3));
    *(float4*)&proj[i] = p;
}

// ================= TF32 tensor-core GEMM =================
// C = A[M,K] @ B[K,N] + bias[N] (+ resid). 128x128x32 block tile,
// 8 warps (2x4), 64x32 warp tile, mma.sync.m16n8k8.tf32, fp32 accum.
// cp.async.cg double-buffered smem (raw fp32), RNA cvt at fragment load.

constexpr int kAPitch = 36;    // As[m][k], (4m+k)%32 distinct -> conflict-free frag loads
constexpr int kBPitch = 132;   // Bs[k][n], (4k+n)%32 distinct -> conflict-free frag loads
constexpr int kASz = 128 * kAPitch;   // floats, one buffer
constexpr int kBSz = 32 * kBPitch;
constexpr int kGemmSmem = 2 * (kASz + kBSz) * 4;   // 70656 bytes

__device__ __forceinline__ void cp16(uint32_t dst, const float* src) {
    asm volatile("cp.async.cg.shared.global [%0], [%1], 16;" :: "r"(dst), "l"(src));
}
__device__ __forceinline__ uint32_t f2tf32(float f) {
    uint32_t u;
    asm("cvt.rna.tf32.f32 %0, %1;" : "=r"(u) : "f"(f));
    return u;
}
__device__ __forceinline__ void mma_tf32(float* c, const uint32_t* a, const uint32_t* b) {
    asm volatile(
        "mma.sync.aligned.m16n8k8.row.col.f32.tf32.tf32.f32 "
        "{%0,%1,%2,%3}, {%4,%5,%6,%7}, {%8,%9}, {%0,%1,%2,%3};"
        : "+f"(c[0]), "+f"(c[1]), "+f"(c[2]), "+f"(c[3])
        : "r"(a[0]), "r"(a[1]), "r"(a[2]), "r"(a[3]), "r"(b[0]), "r"(b[1]));
}

__global__ void __launch_bounds__(256, 2)
gemm_tf32_kernel(const float* __restrict__ A, const float* __restrict__ Bw,
                 const float* __restrict__ bias, const float* __restrict__ resid,
                 float* __restrict__ C, int M, int N, int K)
{
    extern __shared__ float sm[];
    float* As = sm;                       // [2][128][kAPitch]
    float* Bs = sm + 2 * kASz;            // [2][32][kBPitch]
    uint32_t asBase = (uint32_t)__cvta_generic_to_shared(As);
    uint32_t bsBase = (uint32_t)__cvta_generic_to_shared(Bs);

    int tid  = threadIdx.x;
    int lane = tid & 31;
    int warp = tid >> 5;
    int wm = warp >> 2;                   // 0..1
    int wn = warp & 3;                    // 0..3
    int bm = blockIdx.y, bn = blockIdx.x;

    const float* Ab = A + (size_t)bm * 128 * K;
    const float* Bb = Bw + (size_t)bn * 128;

    // cp.async source/dest decomposition (4 chunks of 16B each for A and B)
    int am[4], ak[4];  uint32_t adst[4];
    int bk[4], bn4[4]; uint32_t bdst[4];
#pragma unroll
    for (int i = 0; i < 4; ++i) {
        int c = i * 256 + tid;
        am[i] = c >> 3;            ak[i]  = (c & 7) * 4;
        bk[i] = c >> 5;            bn4[i] = (c & 31) * 4;
        adst[i] = asBase + (uint32_t)(am[i] * kAPitch + ak[i]) * 4u;
        bdst[i] = bsBase + (uint32_t)(bk[i] * kBPitch + bn4[i]) * 4u;
    }

    float acc[4][4][4];
#pragma unroll
    for (int mt = 0; mt < 4; ++mt)
#pragma unroll
        for (int nt = 0; nt < 4; ++nt)
#pragma unroll
            for (int r = 0; r < 4; ++r) acc[mt][nt][r] = 0.0f;

    int nit = K >> 5;   // K/32

    // prologue: stage iter 0 into buffer 0
#pragma unroll
    for (int i = 0; i < 4; ++i) {
        cp16(adst[i], &Ab[(size_t)am[i] * K + ak[i]]);
        cp16(bdst[i], &Bb[(size_t)bk[i] * N + bn4[i]]);
    }
    asm volatile("cp.async.commit_group;");

    for (int it = 0; it < nit; ++it) {
        int buf = it & 1;
        if (it + 1 < nit) {
            int k0 = (it + 1) << 5;
            uint32_t boff = (uint32_t)((buf ^ 1) ? (kASz * 4) : 0);
            uint32_t boffB = (uint32_t)((buf ^ 1) ? (kBSz * 4) : 0);
#pragma unroll
            for (int i = 0; i < 4; ++i) {
                cp16(adst[i] + boff,  &Ab[(size_t)am[i] * K + k0 + ak[i]]);
                cp16(bdst[i] + boffB, &Bb[(size_t)(k0 + bk[i]) * N + bn4[i]]);
            }
            asm volatile("cp.async.commit_group;");
            asm volatile("cp.async.wait_group 1;");
        } else {
            asm volatile("cp.async.wait_group 0;");
        }
        __syncthreads();

        const float* Ac = As + buf * kASz;
        const float* Bc = Bs + buf * kBSz;
#pragma unroll
        for (int ks = 0; ks < 4; ++ks) {
            uint32_t afr[4][4], bfr[4][2];
            int kk = ks * 8 + (lane & 3);
            int mrow = wm * 64 + (lane >> 2);
#pragma unroll
            for (int mt = 0; mt < 4; ++mt) {
                int m0 = mrow + mt * 16;
                afr[mt][0] = f2tf32(Ac[m0 * kAPitch + kk]);
                afr[mt][1] = f2tf32(Ac[(m0 + 8) * kAPitch + kk]);
                afr[mt][2] = f2tf32(Ac[m0 * kAPitch + kk + 4]);
                afr[mt][3] = f2tf32(Ac[(m0 + 8) * kAPitch + kk + 4]);
            }
            int ncol = wn * 32 + (lane >> 2);
#pragma unroll
            for (int nt = 0; nt < 4; ++nt) {
                int n0 = ncol + nt * 8;
                bfr[nt][0] = f2tf32(Bc[kk * kBPitch + n0]);
                bfr[nt][1] = f2tf32(Bc[(kk + 4) * kBPitch + n0]);
            }
#pragma unroll
            for (int mt = 0; mt < 4; ++mt)
#pragma unroll
                for (int nt = 0; nt < 4; ++nt)
                    mma_tf32(acc[mt][nt], afr[mt], bfr[nt]);
        }
        __syncthreads();
    }

    // epilogue: bias (+resid) and store, float2 per fragment half
    int rb = bm * 128 + wm * 64 + (lane >> 2);
    int cb = bn * 128 + wn * 32 + (lane & 3) * 2;
#pragma unroll
    for (int mt = 0; mt < 4; ++mt) {
#pragma unroll
        for (int nt = 0; nt < 4; ++nt) {
            int r0 = rb + mt * 16;
            int c0 = cb + nt * 8;
            float b0 = bias[c0], b1 = bias[c0 + 1];
            size_t off0 = (size_t)r0 * N + c0;
            size_t off1 = (size_t)(r0 + 8) * N + c0;
            float v0 = acc[mt][nt][0] + b0, v1 = acc[mt][nt][1] + b1;
            float v2 = acc[mt][nt][2] + b0, v3 = acc[mt][nt][3] + b1;
            if (resid) {
                float2 rr0 = *(const float2*)&resid[off0];
                float2 rr1 = *(const float2*)&resid[off1];
                v0 += rr0.x; v1 += rr0.y; v2 += rr1.x; v3 += rr1.y;
            }
            *(float2*)&C[off0] = make_float2(v0, v1);
            *(float2*)&C[off1] = make_float2(v2, v3);
        }
    }
}

// ---------------- flash attention (causal, dh=64, 64-query tiles, fp32) ----------------
constexpr int kFlashSmem = (2 * 64 * 65 + 64 * 68 + 64 * 65) * 4;  // 67328 bytes

__global__ void __launch_bounds__(256)
flash_attn_kernel(const float* __restrict__ Q, const float* __restrict__ K,
                  const float* __restrict__ Vv, float* __restrict__ O)
{
    extern __shared__ float sm[];
    float* Qs = sm;
    float* Ks = sm + 64 * 65;
    float* Vs = sm + 2 * 64 * 65;
    float* Ps = Vs + 64 * 68;

    int bh = blockIdx.y;
    int b  = bh / kH;
    int h  = bh % kH;
    int q0 = blockIdx.x * 64;
    int tid = threadIdx.x;
    int tx = tid & 15, ty = tid >> 4;
    size_t base = ((size_t)b * kL) * kD + (size_t)h * kDH;

#pragma unroll
    for (int rr = 0; rr < 4; ++rr) {
        int r = (tid >> 4) + rr * 16;
        int j = (tid & 15) * 4;
        float4 qv = *(const float4*)&Q[base + (size_t)(q0 + r) * kD + j];
        Qs[(j + 0) * 65 + r] = qv.x; Qs[(j + 1) * 65 + r] = qv.y;
        Qs[(j + 2) * 65 + r] = qv.z; Qs[(j + 3) * 65 + r] = qv.w;
    }

    float o[4][4];
    float m[4], lsum[4];
#pragma unroll
    for (int r = 0; r < 4; ++r) {
        m[r] = -1e30f; lsum[r] = 0.0f;
#pragma unroll
        for (int c = 0; c < 4; ++c) o[r][c] = 0.0f;
    }

    int nkt = blockIdx.x + 1;
    for (int kt = 0; kt < nkt; ++kt) {
        int k0 = kt * 64;
        __syncthreads();
#pragma unroll
        for (int rr = 0; rr < 4; ++rr) {
            int r = (tid >> 4) + rr * 16;
            int j = (tid & 15) * 4;
            float4 kv = *(const float4*)&K[base + (size_t)(k0 + r) * kD + j];
            Ks[(j + 0) * 65 + r] = kv.x; Ks[(j + 1) * 65 + r] = kv.y;
            Ks[(j + 2) * 65 + r] = kv.z; Ks[(j + 3) * 65 + r] = kv.w;
            float4 vv = *(const float4*)&Vv[base + (size_t)(k0 + r) * kD + j];
            *(float4*)&Vs[r * 68 + j] = vv;
        }
        __syncthreads();

        float s[4][4];
#pragma unroll
        for (int r = 0; r < 4; ++r)
#pragma unroll
            for (int c = 0; c < 4; ++c) s[r][c] = 0.0f;
#pragma unroll
        for (int j = 0; j < kDH; ++j) {
            float a0 = Qs[j * 65 + ty * 4 + 0];
            float a1 = Qs[j * 65 + ty * 4 + 1];
            float a2 = Qs[j * 65 + ty * 4 + 2];
            float a3 = Qs[j * 65 + ty * 4 + 3];
            float b0 = Ks[j * 65 + tx * 4 + 0];
            float b1 = Ks[j * 65 + tx * 4 + 1];
            float b2 = Ks[j * 65 + tx * 4 + 2];
            float b3 = Ks[j * 65 + tx * 4 + 3];
            s[0][0] = fmaf(a0, b0, s[0][0]); s[0][1] = fmaf(a0, b1, s[0][1]);
            s[0][2] = fmaf(a0, b2, s[0][2]); s[0][3] = fmaf(a0, b3, s[0][3]);
            s[1][0] = fmaf(a1, b0, s[1][0]); s[1][1] = fmaf(a1, b1, s[1][1]);
            s[1][2] = fmaf(a1, b2, s[1][2]); s[1][3] = fmaf(a1, b3, s[1][3]);
            s[2][0] = fmaf(a2, b0, s[2][0]); s[2][1] = fmaf(a2, b1, s[2][1]);
            s[2][2] = fmaf(a2, b2, s[2][2]); s[2][3] = fmaf(a2, b3, s[2][3]);
            s[3][0] = fmaf(a3, b0, s[3][0]); s[3][1] = fmaf(a3, b1, s[3][1]);
            s[3][2] = fmaf(a3, b2, s[3][2]); s[3][3] = fmaf(a3, b3, s[3][3]);
        }

        bool diag = (kt == blockIdx.x);
#pragma unroll
        for (int r = 0; r < 4; ++r)
#pragma unroll
            for (int c = 0; c < 4; ++c) {
                float sv = s[r][c] * 0.125f;
                if (diag && (k0 + tx * 4 + c > q0 + ty * 4 + r)) sv = -1e30f;
                s[r][c] = sv;
            }

        float corr[4];
#pragma unroll
        for (int r = 0; r < 4; ++r) {
            float rm = fmaxf(fmaxf(s[r][0], s[r][1]), fmaxf(s[r][2], s[r][3]));
#pragma unroll
            for (int off = 8; off; off >>= 1)
                rm = fmaxf(rm, __shfl_xor_sync(0xffffffffu, rm, off));
            float mn = fmaxf(m[r], rm);
            corr[r] = __expf(m[r] - mn);
            m[r] = mn;
        }
        float rs[4];
#pragma unroll
        for (int r = 0; r < 4; ++r) {
            rs[r] = 0.0f;
#pragma unroll
            for (int c = 0; c < 4; ++c) {
                float p = __expf(s[r][c] - m[r]);
                Ps[(tx * 4 + c) * 65 + ty * 4 + r] = p;
                rs[r] += p;
            }
#pragma unroll
            for (int off = 8; off; off >>= 1)
                rs[r] += __shfl_xor_sync(0xffffffffu, rs[r], off);
            lsum[r] = lsum[r] * corr[r] + rs[r];
#pragma unroll
            for (int c = 0; c < 4; ++c) o[r][c] *= corr[r];
        }
        __syncthreads();

#pragma unroll
        for (int key = 0; key < 64; ++key) {
            float pa0 = Ps[key * 65 + ty * 4 + 0];
            float pa1 = Ps[key * 65 + ty * 4 + 1];
            float pa2 = Ps[key * 65 + ty * 4 + 2];
            float pa3 = Ps[key * 65 + ty * 4 + 3];
            float vb0 = Vs[key * 68 + tx * 4 + 0];
            float vb1 = Vs[key * 68 + tx * 4 + 1];
            float vb2 = Vs[key * 68 + tx * 4 + 2];
            float vb3 = Vs[key * 68 + tx * 4 + 3];
            o[0][0] = fmaf(pa0, vb0, o[0][0]); o[0][1] = fmaf(pa0, vb1, o[0][1]);
            o[0][2] = fmaf(pa0, vb2, o[0][2]); o[0][3] = fmaf(pa0, vb3, o[0][3]);
            o[1][0] = fmaf(pa1, vb0, o[1][0]); o[1][1] = fmaf(pa1, vb1, o[1][1]);
            o[1][2] = fmaf(pa1, vb2, o[1][2]); o[1][3] = fmaf(pa1, vb3, o[1][3]);
            o[2][0] = fmaf(pa2, vb0, o[2][0]); o[2][1] = fmaf(pa2, vb1, o[2][1]);
            o[2][2] = fmaf(pa2, vb2, o[2][2]); o[2][3] = fmaf(pa2, vb3, o[2][3]);
            o[3][0] = fmaf(pa3, vb0, o[3][0]); o[3][1] = fmaf(pa3, vb1, o[3][1]);
            o[3][2] = fmaf(pa3, vb2, o[3][2]); o[3][3] = fmaf(pa3, vb3, o[3][3]);
        }
    }

#pragma unroll
    for (int r = 0; r < 4; ++r) {
        float inv = 1.0f / lsum[r];
        int gr = q0 + ty * 4 + r;
        float4 ov = make_float4(o[r][0] * inv, o[r][1] * inv, o[r][2] * inv, o[r][3] * inv);
        *(float4*)&O[base + (size_t)gr * kD + tx * 4] = ov;
    }
}

// ---------------- host launcher ----------------
static void launch_gemm(const float* A, const float* B, const float* bias,
                        const float* resid, float* C, int M, int N, int K)
{
    dim3 grid(N / 128, M / 128);
    gemm_tf32_kernel<<<grid, 256, kGemmSmem>>>(A, B, bias, resid, C, M, N, K);
}

extern "C" void kernel_launch(void* const* d_in, const int* in_sizes, int n_in,
                              void* d_out, int out_size)
{
    const int*   ids    = (const int*)  d_in[0];
    const float* embed  = (const float*)d_in[1];
    const float* Wq     = (const float*)d_in[2];
    const float* bq     = (const float*)d_in[3];
    const float* Wk     = (const float*)d_in[4];
    const float* bk     = (const float*)d_in[5];
    const float* Wv     = (const float*)d_in[6];
    const float* bv     = (const float*)d_in[7];
    const float* Wo     = (const float*)d_in[8];
    const float* bo     = (const float*)d_in[9];
    const float* Wproj  = (const float*)d_in[10];
    const float* bproj  = (const float*)d_in[11];
    const float* Wup    = (const float*)d_in[12];
    const float* bup    = (const float*)d_in[13];
    const float* Wdown  = (const float*)d_in[14];
    const float* bdown  = (const float*)d_in[15];
    const float* gammas = (const float*)d_in[16];
    const float* Wlog   = (const float*)d_in[17];
    const float* blog   = (const float*)d_in[18];
    float* out = (float*)d_out;

    float *x, *h, *q, *k, *v, *att, *proj, *up;
    cudaGetSymbolAddress((void**)&x,    g_x);
    cudaGetSymbolAddress((void**)&h,    g_h);
    cudaGetSymbolAddress((void**)&q,    g_q);
    cudaGetSymbolAddress((void**)&k,    g_k);
    cudaGetSymbolAddress((void**)&v,    g_v);
    cudaGetSymbolAddress((void**)&att,  g_att);
    cudaGetSymbolAddress((void**)&proj, g_proj);
    cudaGetSymbolAddress((void**)&up,   g_up);

    cudaFuncSetAttribute(flash_attn_kernel,
                         cudaFuncAttributeMaxDynamicSharedMemorySize, kFlashSmem);
    cudaFuncSetAttribute(gemm_tf32_kernel,
                         cudaFuncAttributeMaxDynamicSharedMemorySize, kGemmSmem);

    embed_pe_kernel<<<kBL, 256>>>(ids, embed, x);

    for (int i = 0; i < kNL; ++i) {
        rmsnorm_kernel<<<kBL, 256>>>(x, gammas + (size_t)(2 * i) * kD, h);
        launch_gemm(h, Wq + (size_t)i * kD * kD, bq + (size_t)i * kD, nullptr, q, kBL, kD, kD);
        launch_gemm(h, Wk + (size_t)i * kD * kD, bk + (size_t)i * kD, nullptr, k, kBL, kD, kD);
        launch_gemm(h, Wv + (size_t)i * kD * kD, bv + (size_t)i * kD, nullptr, v, kBL, kD, kD);
        flash_attn_kernel<<<dim3(kL / 64, kB * kH), 256, kFlashSmem>>>(q, k, v, att);
        launch_gemm(att, Wo + (size_t)i * kD * kD, bo + (size_t)i * kD, x, x, kBL, kD, kD);
        rmsnorm_kernel<<<kBL, 256>>>(x, gammas + (size_t)(2 * i + 1) * kD, h);
        launch_gemm(h, Wproj + (size_t)i * kD * kD2, bproj + (size_t)i * kD2, nullptr, proj, kBL, kD2, kD);
        launch_gemm(h, Wup + (size_t)i * kD * kD2, bup + (size_t)i * kD2, nullptr, up, kBL, kD2, kD);
        silu_gate_kernel<<<((size_t)kBL * kD2) / (256 * 4), 256>>>(proj, up);
        launch_gemm(proj, Wdown + (size_t)i * kD2 * kD, bdown + (size_t)i * kD, x, x, kBL, kD, kD2);
    }
    launch_gemm(x, Wlog, blog, nullptr, out, kBL, kV, kD);
}